// round 5
// baseline (speedup 1.0000x reference)
#include <cuda_runtime.h>
#include <cuda_fp16.h>
#include <cstdint>

// ============================================================================
// RPNHead, sm_103 classic tensor path (mma.sync.m16n8k16 + cp.async + ldmatrix)
// R5: conv re-tiled to 64x64 warp tiles (8 warps / 256 thr, CTA 128x256),
//     3-stage cp.async pipeline, single __syncthreads per K-chunk.
// ============================================================================
#define DB 8
#define DH 128
#define DW 128
#define NPOS (DB*DH*DW)            // 131072
#define OFF_PROBS  3932160
#define OFF_DELTAS 7864320

__device__ __align__(1024) __half g_xh[(size_t)NPOS*256];   // x fp16 [pos][c]
__device__ __align__(1024) __half g_sh[(size_t)NPOS*512];   // shared acts fp16
__device__ __align__(1024) __half g_wt[(size_t)512*2304];   // conv W [n][k]
__device__ __align__(1024) __half g_wh[(size_t)128*512];    // head W [j][c]

__device__ __forceinline__ uint32_t smem_u32(const void* p) {
    uint32_t a;
    asm("{ .reg .u64 t; cvta.to.shared.u64 t, %1; cvt.u32.u64 %0, t; }"
        : "=r"(a) : "l"(p));
    return a;
}

#define CP_ASYNC16(dst, src, sz) \
    asm volatile("cp.async.cg.shared.global [%0], [%1], 16, %2;" \
        :: "r"((uint32_t)(dst)), "l"(src), "r"((int)(sz)) : "memory")
#define CP_COMMIT() asm volatile("cp.async.commit_group;" ::: "memory")
#define CP_WAIT1()  asm volatile("cp.async.wait_group 1;" ::: "memory")
#define CP_WAIT0()  asm volatile("cp.async.wait_group 0;" ::: "memory")

__device__ __forceinline__ void ldm4(uint32_t* f, uint32_t addr) {
    asm volatile("ldmatrix.sync.aligned.m8n8.x4.shared.b16 {%0,%1,%2,%3}, [%4];"
        : "=r"(f[0]), "=r"(f[1]), "=r"(f[2]), "=r"(f[3]) : "r"(addr));
}
__device__ __forceinline__ void mma16816(float* c, const uint32_t* a,
                                         uint32_t b0, uint32_t b1) {
    asm volatile("mma.sync.aligned.m16n8k16.row.col.f32.f16.f16.f32 "
        "{%0,%1,%2,%3}, {%4,%5,%6,%7}, {%8,%9}, {%0,%1,%2,%3};"
        : "+f"(c[0]), "+f"(c[1]), "+f"(c[2]), "+f"(c[3])
        : "r"(a[0]), "r"(a[1]), "r"(a[2]), "r"(a[3]), "r"(b0), "r"(b1));
}

// ============================================================================
// Kernel 1: x fp32 -> fp16
// ============================================================================
__global__ void cvt_x_kernel(const float4* __restrict__ in) {
    int i = blockIdx.x * 256 + threadIdx.x;
    float4 f = in[i];
    __half2 a = __floats2half2_rn(f.x, f.y);
    __half2 b = __floats2half2_rn(f.z, f.w);
    uint2 v;
    v.x = *reinterpret_cast<uint32_t*>(&a);
    v.y = *reinterpret_cast<uint32_t*>(&b);
    reinterpret_cast<uint2*>(g_xh)[i] = v;
}

// ============================================================================
// Kernel 2: weight repack
// ============================================================================
__global__ void cvt_w_kernel(const float* __restrict__ ws, const float* __restrict__ wc,
                             const float* __restrict__ wr) {
    int k = blockIdx.x;          // 0..2303
    int n = threadIdx.x;         // 0..511
    g_wt[(size_t)n * 2304 + k] = __float2half(ws[(size_t)k * 512 + n]);
    if (k < 128) {
        int j = k, c = n;
        float v = 0.0f;
        if (j < 30)      v = wc[c * 30 + j];
        else if (j < 90) v = wr[c * 60 + (j - 30)];
        g_wh[(size_t)j * 512 + c] = __float2half(v);
    }
}

// ============================================================================
// Kernel 3: conv 3x3 (256->512) + bias + relu6, implicit GEMM.
// grid = 2048: blockIdx>>1 = (b*128+h), blockIdx&1 = n-half.
// 256 threads = 8 warps (2m x 4n), warp tile 64x64, CTA 128(M=w) x 256(N).
// K = 36 chunks of 64. 3-stage pipeline, one sync per chunk.
// SMEM: (16KB A + 32KB B) * 3 stages + 1KB bias = 148480 B.
// ============================================================================
#define CV_STG     49152u
#define CV_A(s)    ((s) * CV_STG)
#define CV_B(s)    ((s) * CV_STG + 16384u)
#define CV_BIAS    147456u
#define CV_SMEM    148480
#define CV_NCH     36

__global__ void __launch_bounds__(256, 1) conv_kernel(const float* __restrict__ bias)
{
    extern __shared__ char sm[];
    const uint32_t sb = smem_u32(sm);
    const int tid = threadIdx.x;
    const int rowid = blockIdx.x >> 1;
    const int n0 = (blockIdx.x & 1) << 8;
    const int b = rowid >> 7, h = rowid & 127;

    float* sbias = reinterpret_cast<float*>(sm + CV_BIAS);
    if (tid < 256) sbias[tid] = bias[n0 + tid];

    // A loads: 128 rows x 128B; 2 threads/row, 4 x 16B each
    const int rowA = tid >> 1;
    const int kgA0 = (tid & 1) * 4;
    const uint32_t swA = (uint32_t)(rowA & 7);
    // B loads: 256 rows x 128B; 1 thread/row, 8 x 16B each
    const int rowB = tid;
    const uint32_t swB = (uint32_t)(rowB & 7);

    // warp geometry: 2 (m) x 4 (n) warps, 64x64 tiles
    const int w = tid >> 5, l = tid & 31;
    const int wm = (w >> 2) * 64, wn = (w & 3) * 64;
    const int lrow = l & 15, hi = l >> 4;
    const uint32_t swL = (uint32_t)(lrow & 7);
    uint32_t aRow[4], bRow[4];
    #pragma unroll
    for (int mt = 0; mt < 4; ++mt) aRow[mt] = (uint32_t)((wm + mt * 16 + lrow) * 128);
    #pragma unroll
    for (int nt = 0; nt < 4; ++nt) bRow[nt] = (uint32_t)((wn + nt * 16 + lrow) * 128);

    float acc[4][8][4];
    #pragma unroll
    for (int mt = 0; mt < 4; ++mt)
        #pragma unroll
        for (int n8 = 0; n8 < 8; ++n8)
            #pragma unroll
            for (int e = 0; e < 4; ++e) acc[mt][n8][e] = 0.0f;

    auto load_chunk = [&](int q, int s) {
        const int tap = q >> 2, ci = q & 3;
        const int kh = tap / 3, kw = tap - kh * 3;
        const int hh = h + kh - 1;
        const int ww = rowA + kw - 1;
        const bool av = (hh >= 0) && (hh < 128) && (ww >= 0) && (ww < 128);
        const int hc = min(max(hh, 0), 127), wc_ = min(max(ww, 0), 127);
        const char* srcA = reinterpret_cast<const char*>(
            g_xh + ((size_t)((b * 128 + hc) * 128 + wc_) * 256 + ci * 64));
        const uint32_t Ab = sb + CV_A(s), Bb = sb + CV_B(s);
        #pragma unroll
        for (int i = 0; i < 4; ++i) {
            const int kg = kgA0 + i;
            CP_ASYNC16(Ab + (uint32_t)rowA * 128 + (((uint32_t)kg ^ swA) << 4),
                       srcA + kg * 16, av ? 16 : 0);
        }
        const char* srcB = reinterpret_cast<const char*>(
            g_wt + (size_t)(n0 + rowB) * 2304 + q * 64);
        #pragma unroll
        for (int i = 0; i < 8; ++i) {
            CP_ASYNC16(Bb + (uint32_t)rowB * 128 + (((uint32_t)i ^ swB) << 4),
                       srcB + i * 16, 16);
        }
    };

    load_chunk(0, 0); CP_COMMIT();
    load_chunk(1, 1); CP_COMMIT();

    #pragma unroll 1
    for (int q = 0; q < CV_NCH; ++q) {
        CP_WAIT1();          // chunk q's group complete
        __syncthreads();     // visible to all; also fences prev iter's reads

        if (q + 2 < CV_NCH) load_chunk(q + 2, (q + 2) % 3);
        CP_COMMIT();         // empty group near tail keeps count consistent

        const uint32_t Ab = sb + CV_A(q % 3), Bb = sb + CV_B(q % 3);
        #pragma unroll
        for (int ks = 0; ks < 4; ++ks) {
            const uint32_t col = (((uint32_t)(ks * 2 + hi)) ^ swL) << 4;
            uint32_t af[4][4], bf[4][4];
            #pragma unroll
            for (int mt = 0; mt < 4; ++mt) ldm4(af[mt], Ab + aRow[mt] + col);
            #pragma unroll
            for (int nt = 0; nt < 4; ++nt) ldm4(bf[nt], Bb + bRow[nt] + col);
            #pragma unroll
            for (int mt = 0; mt < 4; ++mt)
                #pragma unroll
                for (int n8 = 0; n8 < 8; ++n8)
                    mma16816(acc[mt][n8], af[mt], bf[n8 >> 1][n8 & 1], bf[n8 >> 1][(n8 & 1) + 2]);
        }
    }

    // epilogue: bias + relu6 -> fp16 scratch
    const int qrow = l >> 2, qcol = (l & 3) * 2;
    #pragma unroll
    for (int mt = 0; mt < 4; ++mt) {
        #pragma unroll
        for (int n8 = 0; n8 < 8; ++n8) {
            const int ch = wn + n8 * 8 + qcol;
            const float b0 = sbias[ch], b1 = sbias[ch + 1];
            #pragma unroll
            for (int hlf = 0; hlf < 2; ++hlf) {
                const int m = wm + mt * 16 + qrow + hlf * 8;
                float v0 = acc[mt][n8][2 * hlf]     + b0;
                float v1 = acc[mt][n8][2 * hlf + 1] + b1;
                v0 = fminf(fmaxf(v0, 0.0f), 6.0f);
                v1 = fminf(fmaxf(v1, 0.0f), 6.0f);
                const size_t pos = (size_t)rowid * 128 + m;
                *reinterpret_cast<__half2*>(g_sh + pos * 512 + n0 + ch) =
                    __floats2half2_rn(v0, v1);
            }
        }
    }
}

// ============================================================================
// Kernel 4: head GEMM M=128/N=128(96 used)/K=512 + bias + softmax + writes.
// grid = 1024, 256 threads = 8 warps (2m x 4n), warp tile 64x32. 8 K-chunks.
// ============================================================================
#define HD_A(buf)  ((buf) * 32768u)
#define HD_B(buf)  ((buf) * 32768u + 16384u)
#define HD_BIAS    65536u
#define HD_SMEM    66048
#define HD_NCH     8

__global__ void __launch_bounds__(256, 1) head_kernel(const float* __restrict__ bc,
                                                      const float* __restrict__ br,
                                                      float* __restrict__ out)
{
    extern __shared__ char sm[];
    const uint32_t sb = smem_u32(sm);
    const int tid = threadIdx.x;
    const size_t pos0 = (size_t)blockIdx.x * 128;

    float* hb = reinterpret_cast<float*>(sm + HD_BIAS);
    if (tid < 128)
        hb[tid] = (tid < 30) ? bc[tid] : (tid < 90 ? br[tid - 30] : 0.0f);

    const int rowT = tid >> 1;
    const int kg0 = (tid * 4) & 7;
    const uint32_t swT = (uint32_t)(rowT & 7);

    const int w = tid >> 5, l = tid & 31;
    const int wm = (w >> 2) * 64, wn = (w & 3) * 32;
    const int lrow = l & 15, hi = l >> 4;
    const uint32_t swL = (uint32_t)(lrow & 7);
    uint32_t aRow[4], bRow[2];
    #pragma unroll
    for (int mt = 0; mt < 4; ++mt) aRow[mt] = (uint32_t)((wm + mt * 16 + lrow) * 128);
    #pragma unroll
    for (int nt = 0; nt < 2; ++nt) bRow[nt] = (uint32_t)((wn + nt * 16 + lrow) * 128);

    float acc[4][4][4];
    #pragma unroll
    for (int mt = 0; mt < 4; ++mt)
        #pragma unroll
        for (int n8 = 0; n8 < 4; ++n8)
            #pragma unroll
            for (int e = 0; e < 4; ++e) acc[mt][n8][e] = 0.0f;

    auto load_chunk = [&](int q, int buf) {
        const uint32_t Ab = sb + HD_A(buf), Bb = sb + HD_B(buf);
        const char* srcA = reinterpret_cast<const char*>(
            g_sh + (pos0 + rowT) * 512 + q * 64);
        const char* srcB = reinterpret_cast<const char*>(
            g_wh + (size_t)rowT * 512 + q * 64);
        #pragma unroll
        for (int i = 0; i < 4; ++i) {
            const int kg = kg0 + i;
            const uint32_t off = (uint32_t)rowT * 128 + (((uint32_t)kg ^ swT) << 4);
            CP_ASYNC16(Ab + off, srcA + kg * 16, 16);
            CP_ASYNC16(Bb + off, srcB + kg * 16, 16);
        }
    };

    load_chunk(0, 0);
    CP_COMMIT();

    #pragma unroll 1
    for (int q = 0; q < HD_NCH; ++q) {
        if (q + 1 < HD_NCH) {
            load_chunk(q + 1, (q + 1) & 1);
            CP_COMMIT();
            CP_WAIT1();
        } else {
            CP_WAIT0();
        }
        __syncthreads();

        const uint32_t Ab = sb + HD_A(q & 1), Bb = sb + HD_B(q & 1);
        #pragma unroll
        for (int ks = 0; ks < 4; ++ks) {
            const uint32_t col = (((uint32_t)(ks * 2 + hi)) ^ swL) << 4;
            uint32_t af[4][4], bf[2][4];
            #pragma unroll
            for (int mt = 0; mt < 4; ++mt) ldm4(af[mt], Ab + aRow[mt] + col);
            #pragma unroll
            for (int nt = 0; nt < 2; ++nt) ldm4(bf[nt], Bb + bRow[nt] + col);
            #pragma unroll
            for (int mt = 0; mt < 4; ++mt)
                #pragma unroll
                for (int n8 = 0; n8 < 4; ++n8)
                    mma16816(acc[mt][n8], af[mt], bf[n8 >> 1][n8 & 1], bf[n8 >> 1][(n8 & 1) + 2]);
        }
        __syncthreads();
    }

    const int qrow = l >> 2, qcol = (l & 3) * 2;
    #pragma unroll
    for (int mt = 0; mt < 4; ++mt) {
        #pragma unroll
        for (int n8 = 0; n8 < 4; ++n8) {
            const int ch = wn + n8 * 8 + qcol;
            if (ch >= 90) continue;
            const float b0 = hb[ch], b1 = hb[ch + 1];
            #pragma unroll
            for (int hlf = 0; hlf < 2; ++hlf) {
                const int m = wm + mt * 16 + qrow + hlf * 8;
                const size_t pos = pos0 + m;
                const float v0 = acc[mt][n8][2 * hlf]     + b0;
                const float v1 = acc[mt][n8][2 * hlf + 1] + b1;
                if (ch < 30) {
                    *reinterpret_cast<float2*>(out + pos * 30 + ch) = make_float2(v0, v1);
                    const float mx = fmaxf(v0, v1);
                    const float e0 = __expf(v0 - mx), e1 = __expf(v1 - mx);
                    const float inv = 1.0f / (e0 + e1);
                    *reinterpret_cast<float2*>(out + OFF_PROBS + pos * 30 + ch) =
                        make_float2(e0 * inv, e1 * inv);
                } else {
                    *reinterpret_cast<float2*>(out + OFF_DELTAS + pos * 60 + (ch - 30)) =
                        make_float2(v0, v1);
                }
            }
        }
    }
}

// ============================================================================
// Launch
// ============================================================================
extern "C" void kernel_launch(void* const* d_in, const int* in_sizes, int n_in,
                              void* d_out, int out_size) {
    const float* x  = (const float*)d_in[0];
    const float* ws = (const float*)d_in[1];
    const float* bs = (const float*)d_in[2];
    const float* wc = (const float*)d_in[3];
    const float* bc = (const float*)d_in[4];
    const float* wr = (const float*)d_in[5];
    const float* br = (const float*)d_in[6];
    float* out = (float*)d_out;

    cudaFuncSetAttribute(conv_kernel, cudaFuncAttributeMaxDynamicSharedMemorySize, CV_SMEM);
    cudaFuncSetAttribute(head_kernel, cudaFuncAttributeMaxDynamicSharedMemorySize, HD_SMEM);

    cvt_x_kernel<<<32768, 256>>>(reinterpret_cast<const float4*>(x));
    cvt_w_kernel<<<2304, 512>>>(ws, wc, wr);
    conv_kernel<<<2048, 256, CV_SMEM>>>(bs);
    head_kernel<<<1024, 256, HD_SMEM>>>(bc, br, out);
}

// round 6
// speedup vs baseline: 1.0234x; 1.0234x over previous
#include <cuda_runtime.h>
#include <cuda_fp16.h>
#include <cstdint>

// ============================================================================
// RPNHead, sm_103 classic tensor path. R6: revert conv to R4 structure
// (512 thr / 16 warps / 64x32 warp tiles, 2-stage cp.async), but accumulate
// each 64-K chunk in fp16 (mma f16.f16.f16.f16, 2x rate hypothesis) and
// promote to fp32 once per chunk.
// ============================================================================
#define DB 8
#define DH 128
#define DW 128
#define NPOS (DB*DH*DW)            // 131072
#define OFF_PROBS  3932160
#define OFF_DELTAS 7864320

__device__ __align__(1024) __half g_xh[(size_t)NPOS*256];   // x fp16 [pos][c]
__device__ __align__(1024) __half g_sh[(size_t)NPOS*512];   // shared acts fp16
__device__ __align__(1024) __half g_wt[(size_t)512*2304];   // conv W [n][k]
__device__ __align__(1024) __half g_wh[(size_t)128*512];    // head W [j][c]

__device__ __forceinline__ uint32_t smem_u32(const void* p) {
    uint32_t a;
    asm("{ .reg .u64 t; cvta.to.shared.u64 t, %1; cvt.u32.u64 %0, t; }"
        : "=r"(a) : "l"(p));
    return a;
}

#define CP_ASYNC16(dst, src, sz) \
    asm volatile("cp.async.cg.shared.global [%0], [%1], 16, %2;" \
        :: "r"((uint32_t)(dst)), "l"(src), "r"((int)(sz)) : "memory")
#define CP_COMMIT() asm volatile("cp.async.commit_group;" ::: "memory")
#define CP_WAIT1()  asm volatile("cp.async.wait_group 1;" ::: "memory")
#define CP_WAIT0()  asm volatile("cp.async.wait_group 0;" ::: "memory")

__device__ __forceinline__ void ldm4(uint32_t* f, uint32_t addr) {
    asm volatile("ldmatrix.sync.aligned.m8n8.x4.shared.b16 {%0,%1,%2,%3}, [%4];"
        : "=r"(f[0]), "=r"(f[1]), "=r"(f[2]), "=r"(f[3]) : "r"(addr));
}
__device__ __forceinline__ void mma16816(float* c, const uint32_t* a,
                                         uint32_t b0, uint32_t b1) {
    asm volatile("mma.sync.aligned.m16n8k16.row.col.f32.f16.f16.f32 "
        "{%0,%1,%2,%3}, {%4,%5,%6,%7}, {%8,%9}, {%0,%1,%2,%3};"
        : "+f"(c[0]), "+f"(c[1]), "+f"(c[2]), "+f"(c[3])
        : "r"(a[0]), "r"(a[1]), "r"(a[2]), "r"(a[3]), "r"(b0), "r"(b1));
}
// fp16-accumulate variant: C fragment = 2 b32 regs (4 halves)
__device__ __forceinline__ void mma16816h(uint32_t* c, const uint32_t* a,
                                          uint32_t b0, uint32_t b1) {
    asm volatile("mma.sync.aligned.m16n8k16.row.col.f16.f16.f16.f16 "
        "{%0,%1}, {%2,%3,%4,%5}, {%6,%7}, {%0,%1};"
        : "+r"(c[0]), "+r"(c[1])
        : "r"(a[0]), "r"(a[1]), "r"(a[2]), "r"(a[3]), "r"(b0), "r"(b1));
}

// ============================================================================
// Kernel 1: x fp32 -> fp16
// ============================================================================
__global__ void cvt_x_kernel(const float4* __restrict__ in) {
    int i = blockIdx.x * 256 + threadIdx.x;
    float4 f = in[i];
    __half2 a = __floats2half2_rn(f.x, f.y);
    __half2 b = __floats2half2_rn(f.z, f.w);
    uint2 v;
    v.x = *reinterpret_cast<uint32_t*>(&a);
    v.y = *reinterpret_cast<uint32_t*>(&b);
    reinterpret_cast<uint2*>(g_xh)[i] = v;
}

// ============================================================================
// Kernel 2: weight repack
// ============================================================================
__global__ void cvt_w_kernel(const float* __restrict__ ws, const float* __restrict__ wc,
                             const float* __restrict__ wr) {
    int k = blockIdx.x;          // 0..2303
    int n = threadIdx.x;         // 0..511
    g_wt[(size_t)n * 2304 + k] = __float2half(ws[(size_t)k * 512 + n]);
    if (k < 128) {
        int j = k, c = n;
        float v = 0.0f;
        if (j < 30)      v = wc[c * 30 + j];
        else if (j < 90) v = wr[c * 60 + (j - 30)];
        g_wh[(size_t)j * 512 + c] = __float2half(v);
    }
}

// ============================================================================
// Kernel 3: conv 3x3 (256->512) + bias + relu6, implicit GEMM.
// grid = 2048: blockIdx>>1 = (b*128+h), blockIdx&1 = n-half (256 wide).
// 512 threads = 16 warps (2m x 8n), warp tile 64x32, K-chunk 64, 2 stages.
// Chunk accumulation in fp16 (4 chained mma), promoted to fp32 per chunk.
// ============================================================================
#define CV_A(buf)  ((buf) * 49152u)
#define CV_B(buf)  ((buf) * 49152u + 16384u)
#define CV_BIAS    98304u
#define CV_SMEM    99328
#define CV_NCH     36

__global__ void __launch_bounds__(512, 1) conv_kernel(const float* __restrict__ bias)
{
    extern __shared__ char sm[];
    const uint32_t sb = smem_u32(sm);
    const int tid = threadIdx.x;
    const int rowid = blockIdx.x >> 1;
    const int n0 = (blockIdx.x & 1) << 8;
    const int b = rowid >> 7, h = rowid & 127;

    float* sbias = reinterpret_cast<float*>(sm + CV_BIAS);
    if (tid < 256) sbias[tid] = bias[n0 + tid];

    // per-thread load geometry (as R4)
    const int rowA = tid >> 2;            // A: 2 16B-groups, one half-row
    const int kgA0 = (tid * 2) & 7;
    const int rowB = tid >> 1;            // B: 4 16B-groups, one half-row
    const int kgB0 = (tid * 4) & 7;
    const uint32_t swA = (uint32_t)(rowA & 7);
    const uint32_t swB = (uint32_t)(rowB & 7);

    // warp geometry: 16 warps = 2(m) x 8(n), warp tile 64x32
    const int w = tid >> 5, l = tid & 31;
    const int wm = (w >> 3) * 64, wn = (w & 7) * 32;
    const int lrow = l & 15, hi = l >> 4;
    const uint32_t swL = (uint32_t)(lrow & 7);
    uint32_t aRow[4], bRow[2];
    #pragma unroll
    for (int mt = 0; mt < 4; ++mt) aRow[mt] = (uint32_t)((wm + mt * 16 + lrow) * 128);
    #pragma unroll
    for (int nt = 0; nt < 2; ++nt) bRow[nt] = (uint32_t)((wn + nt * 16 + lrow) * 128);

    float acc[4][4][4];
    #pragma unroll
    for (int mt = 0; mt < 4; ++mt)
        #pragma unroll
        for (int n8 = 0; n8 < 4; ++n8)
            #pragma unroll
            for (int e = 0; e < 4; ++e) acc[mt][n8][e] = 0.0f;

    auto load_chunk = [&](int q, int buf) {
        const int tap = q >> 2, ci = q & 3;
        const int kh = tap / 3, kw = tap - kh * 3;
        const int hh = h + kh - 1;
        const int ww = rowA + kw - 1;
        const bool av = (hh >= 0) && (hh < 128) && (ww >= 0) && (ww < 128);
        const int hc = min(max(hh, 0), 127), wc_ = min(max(ww, 0), 127);
        const char* srcA = reinterpret_cast<const char*>(
            g_xh + ((size_t)((b * 128 + hc) * 128 + wc_) * 256 + ci * 64));
        const uint32_t Ab = sb + CV_A(buf), Bb = sb + CV_B(buf);
        #pragma unroll
        for (int i = 0; i < 2; ++i) {
            const int kg = kgA0 + i;
            CP_ASYNC16(Ab + (uint32_t)rowA * 128 + (((uint32_t)kg ^ swA) << 4),
                       srcA + kg * 16, av ? 16 : 0);
        }
        const char* srcB = reinterpret_cast<const char*>(
            g_wt + (size_t)(n0 + rowB) * 2304 + q * 64);
        #pragma unroll
        for (int i = 0; i < 4; ++i) {
            const int kg = kgB0 + i;
            CP_ASYNC16(Bb + (uint32_t)rowB * 128 + (((uint32_t)kg ^ swB) << 4),
                       srcB + kg * 16, 16);
        }
    };

    load_chunk(0, 0);
    CP_COMMIT();

    #pragma unroll 1
    for (int q = 0; q < CV_NCH; ++q) {
        if (q + 1 < CV_NCH) {
            load_chunk(q + 1, (q + 1) & 1);
            CP_COMMIT();
            CP_WAIT1();
        } else {
            CP_WAIT0();
        }
        __syncthreads();

        const uint32_t Ab = sb + CV_A(q & 1), Bb = sb + CV_B(q & 1);

        // two mt-halves to cap live fp16 fragments at 16 regs
        #pragma unroll
        for (int half = 0; half < 2; ++half) {
            uint32_t hc[2][4][2];
            #pragma unroll
            for (int mtl = 0; mtl < 2; ++mtl)
                #pragma unroll
                for (int n8 = 0; n8 < 4; ++n8)
                    hc[mtl][n8][0] = hc[mtl][n8][1] = 0u;

            #pragma unroll
            for (int ks = 0; ks < 4; ++ks) {
                const uint32_t col = (((uint32_t)(ks * 2 + hi)) ^ swL) << 4;
                uint32_t af[2][4], bf[2][4];
                #pragma unroll
                for (int mtl = 0; mtl < 2; ++mtl)
                    ldm4(af[mtl], Ab + aRow[half * 2 + mtl] + col);
                #pragma unroll
                for (int nt = 0; nt < 2; ++nt)
                    ldm4(bf[nt], Bb + bRow[nt] + col);
                #pragma unroll
                for (int mtl = 0; mtl < 2; ++mtl)
                    #pragma unroll
                    for (int n8 = 0; n8 < 4; ++n8)
                        mma16816h(hc[mtl][n8], af[mtl],
                                  bf[n8 >> 1][n8 & 1], bf[n8 >> 1][(n8 & 1) + 2]);
            }

            // promote chunk partials to fp32
            #pragma unroll
            for (int mtl = 0; mtl < 2; ++mtl)
                #pragma unroll
                for (int n8 = 0; n8 < 4; ++n8) {
                    float* a4 = acc[half * 2 + mtl][n8];
                    const float2 p0 = __half22float2(
                        *reinterpret_cast<__half2*>(&hc[mtl][n8][0]));
                    const float2 p1 = __half22float2(
                        *reinterpret_cast<__half2*>(&hc[mtl][n8][1]));
                    a4[0] += p0.x; a4[1] += p0.y;
                    a4[2] += p1.x; a4[3] += p1.y;
                }
        }
        __syncthreads();
    }

    // epilogue: bias + relu6 -> fp16 scratch
    const int qrow = l >> 2, qcol = (l & 3) * 2;
    #pragma unroll
    for (int mt = 0; mt < 4; ++mt) {
        #pragma unroll
        for (int n8 = 0; n8 < 4; ++n8) {
            const int ch = wn + n8 * 8 + qcol;
            const float b0 = sbias[ch], b1 = sbias[ch + 1];
            #pragma unroll
            for (int hlf = 0; hlf < 2; ++hlf) {
                const int m = wm + mt * 16 + qrow + hlf * 8;
                float v0 = acc[mt][n8][2 * hlf]     + b0;
                float v1 = acc[mt][n8][2 * hlf + 1] + b1;
                v0 = fminf(fmaxf(v0, 0.0f), 6.0f);
                v1 = fminf(fmaxf(v1, 0.0f), 6.0f);
                const size_t pos = (size_t)rowid * 128 + m;
                *reinterpret_cast<__half2*>(g_sh + pos * 512 + n0 + ch) =
                    __floats2half2_rn(v0, v1);
            }
        }
    }
}

// ============================================================================
// Kernel 4: head GEMM M=128/N=128(96 used)/K=512 + bias + softmax + writes.
// grid = 1024, 256 threads = 8 warps (2m x 4n), warp tile 64x32. 8 K-chunks.
// ============================================================================
#define HD_A(buf)  ((buf) * 32768u)
#define HD_B(buf)  ((buf) * 32768u + 16384u)
#define HD_BIAS    65536u
#define HD_SMEM    66048
#define HD_NCH     8

__global__ void __launch_bounds__(256, 1) head_kernel(const float* __restrict__ bc,
                                                      const float* __restrict__ br,
                                                      float* __restrict__ out)
{
    extern __shared__ char sm[];
    const uint32_t sb = smem_u32(sm);
    const int tid = threadIdx.x;
    const size_t pos0 = (size_t)blockIdx.x * 128;

    float* hb = reinterpret_cast<float*>(sm + HD_BIAS);
    if (tid < 128)
        hb[tid] = (tid < 30) ? bc[tid] : (tid < 90 ? br[tid - 30] : 0.0f);

    const int rowT = tid >> 1;
    const int kg0 = (tid * 4) & 7;
    const uint32_t swT = (uint32_t)(rowT & 7);

    const int w = tid >> 5, l = tid & 31;
    const int wm = (w >> 2) * 64, wn = (w & 3) * 32;
    const int lrow = l & 15, hi = l >> 4;
    const uint32_t swL = (uint32_t)(lrow & 7);
    uint32_t aRow[4], bRow[2];
    #pragma unroll
    for (int mt = 0; mt < 4; ++mt) aRow[mt] = (uint32_t)((wm + mt * 16 + lrow) * 128);
    #pragma unroll
    for (int nt = 0; nt < 2; ++nt) bRow[nt] = (uint32_t)((wn + nt * 16 + lrow) * 128);

    float acc[4][4][4];
    #pragma unroll
    for (int mt = 0; mt < 4; ++mt)
        #pragma unroll
        for (int n8 = 0; n8 < 4; ++n8)
            #pragma unroll
            for (int e = 0; e < 4; ++e) acc[mt][n8][e] = 0.0f;

    auto load_chunk = [&](int q, int buf) {
        const uint32_t Ab = sb + HD_A(buf), Bb = sb + HD_B(buf);
        const char* srcA = reinterpret_cast<const char*>(
            g_sh + (pos0 + rowT) * 512 + q * 64);
        const char* srcB = reinterpret_cast<const char*>(
            g_wh + (size_t)rowT * 512 + q * 64);
        #pragma unroll
        for (int i = 0; i < 4; ++i) {
            const int kg = kg0 + i;
            const uint32_t off = (uint32_t)rowT * 128 + (((uint32_t)kg ^ swT) << 4);
            CP_ASYNC16(Ab + off, srcA + kg * 16, 16);
            CP_ASYNC16(Bb + off, srcB + kg * 16, 16);
        }
    };

    load_chunk(0, 0);
    CP_COMMIT();

    #pragma unroll 1
    for (int q = 0; q < HD_NCH; ++q) {
        if (q + 1 < HD_NCH) {
            load_chunk(q + 1, (q + 1) & 1);
            CP_COMMIT();
            CP_WAIT1();
        } else {
            CP_WAIT0();
        }
        __syncthreads();

        const uint32_t Ab = sb + HD_A(q & 1), Bb = sb + HD_B(q & 1);
        #pragma unroll
        for (int ks = 0; ks < 4; ++ks) {
            const uint32_t col = (((uint32_t)(ks * 2 + hi)) ^ swL) << 4;
            uint32_t af[4][4], bf[2][4];
            #pragma unroll
            for (int mt = 0; mt < 4; ++mt) ldm4(af[mt], Ab + aRow[mt] + col);
            #pragma unroll
            for (int nt = 0; nt < 2; ++nt) ldm4(bf[nt], Bb + bRow[nt] + col);
            #pragma unroll
            for (int mt = 0; mt < 4; ++mt)
                #pragma unroll
                for (int n8 = 0; n8 < 4; ++n8)
                    mma16816(acc[mt][n8], af[mt], bf[n8 >> 1][n8 & 1], bf[n8 >> 1][(n8 & 1) + 2]);
        }
        __syncthreads();
    }

    const int qrow = l >> 2, qcol = (l & 3) * 2;
    #pragma unroll
    for (int mt = 0; mt < 4; ++mt) {
        #pragma unroll
        for (int n8 = 0; n8 < 4; ++n8) {
            const int ch = wn + n8 * 8 + qcol;
            if (ch >= 90) continue;
            const float b0 = hb[ch], b1 = hb[ch + 1];
            #pragma unroll
            for (int hlf = 0; hlf < 2; ++hlf) {
                const int m = wm + mt * 16 + qrow + hlf * 8;
                const size_t pos = pos0 + m;
                const float v0 = acc[mt][n8][2 * hlf]     + b0;
                const float v1 = acc[mt][n8][2 * hlf + 1] + b1;
                if (ch < 30) {
                    *reinterpret_cast<float2*>(out + pos * 30 + ch) = make_float2(v0, v1);
                    const float mx = fmaxf(v0, v1);
                    const float e0 = __expf(v0 - mx), e1 = __expf(v1 - mx);
                    const float inv = 1.0f / (e0 + e1);
                    *reinterpret_cast<float2*>(out + OFF_PROBS + pos * 30 + ch) =
                        make_float2(e0 * inv, e1 * inv);
                } else {
                    *reinterpret_cast<float2*>(out + OFF_DELTAS + pos * 60 + (ch - 30)) =
                        make_float2(v0, v1);
                }
            }
        }
    }
}

// ============================================================================
// Launch
// ============================================================================
extern "C" void kernel_launch(void* const* d_in, const int* in_sizes, int n_in,
                              void* d_out, int out_size) {
    const float* x  = (const float*)d_in[0];
    const float* ws = (const float*)d_in[1];
    const float* bs = (const float*)d_in[2];
    const float* wc = (const float*)d_in[3];
    const float* bc = (const float*)d_in[4];
    const float* wr = (const float*)d_in[5];
    const float* br = (const float*)d_in[6];
    float* out = (float*)d_out;

    cudaFuncSetAttribute(conv_kernel, cudaFuncAttributeMaxDynamicSharedMemorySize, CV_SMEM);
    cudaFuncSetAttribute(head_kernel, cudaFuncAttributeMaxDynamicSharedMemorySize, HD_SMEM);

    cvt_x_kernel<<<32768, 256>>>(reinterpret_cast<const float4*>(x));
    cvt_w_kernel<<<2304, 512>>>(ws, wc, wr);
    conv_kernel<<<2048, 512, CV_SMEM>>>(bs);
    head_kernel<<<1024, 256, HD_SMEM>>>(bc, br, out);
}

// round 7
// speedup vs baseline: 1.5930x; 1.5566x over previous
#include <cuda_runtime.h>
#include <cuda_fp16.h>
#include <cstdint>

// ============================================================================
// RPNHead via Winograd F(2x2,3x3) for the 3x3 conv (2.25x FLOP cut), then
// 1x1 head GEMM. Legacy tensor path (mma.sync m16n8k16 + cp.async + ldmatrix,
// proven fragment maps from R4). M (GEMM output) kept in fp32 for accuracy.
//
//  V = Bt d B   (input tiles,  fp32 compute -> fp16)   [16][32768][256]
//  U = G g Gt   (weights,      fp32 compute -> fp16)   [16][512][256]
//  M[comp]  = V[comp] x U[comp]^T  (16 GEMMs, fp32 out) [16][32768][512]
//  Y = At M A + bias, relu6  -> g_sh fp16               [131072][512]
//  head: 1x1 conv (30 cls / 60 reg) + softmax pairs -> out
// ============================================================================
#define NPOS 131072
#define NTIL 32768
#define OFF_PROBS  3932160
#define OFF_DELTAS 7864320

__device__ __align__(1024) __half g_V [(size_t)16*NTIL*256];   // input transform
__device__ __align__(1024) __half g_wU[(size_t)16*512*256];    // weight transform
__device__ __align__(1024) float  g_M [(size_t)16*NTIL*512];   // GEMM results
__device__ __align__(1024) __half g_sh[(size_t)NPOS*512];      // shared acts fp16
__device__ __align__(1024) __half g_wh[(size_t)128*512];       // head W [j][c]

__device__ __forceinline__ uint32_t smem_u32(const void* p) {
    uint32_t a;
    asm("{ .reg .u64 t; cvta.to.shared.u64 t, %1; cvt.u32.u64 %0, t; }"
        : "=r"(a) : "l"(p));
    return a;
}

#define CP_ASYNC16(dst, src, sz) \
    asm volatile("cp.async.cg.shared.global [%0], [%1], 16, %2;" \
        :: "r"((uint32_t)(dst)), "l"(src), "r"((int)(sz)) : "memory")
#define CP_COMMIT() asm volatile("cp.async.commit_group;" ::: "memory")
#define CP_WAIT1()  asm volatile("cp.async.wait_group 1;" ::: "memory")
#define CP_WAIT0()  asm volatile("cp.async.wait_group 0;" ::: "memory")

__device__ __forceinline__ void ldm4(uint32_t* f, uint32_t addr) {
    asm volatile("ldmatrix.sync.aligned.m8n8.x4.shared.b16 {%0,%1,%2,%3}, [%4];"
        : "=r"(f[0]), "=r"(f[1]), "=r"(f[2]), "=r"(f[3]) : "r"(addr));
}
__device__ __forceinline__ void mma16816(float* c, const uint32_t* a,
                                         uint32_t b0, uint32_t b1) {
    asm volatile("mma.sync.aligned.m16n8k16.row.col.f32.f16.f16.f32 "
        "{%0,%1,%2,%3}, {%4,%5,%6,%7}, {%8,%9}, {%0,%1,%2,%3};"
        : "+f"(c[0]), "+f"(c[1]), "+f"(c[2]), "+f"(c[3])
        : "r"(a[0]), "r"(a[1]), "r"(a[2]), "r"(a[3]), "r"(b0), "r"(b1));
}

// ============================================================================
// Kernel 1: input transform V = Bt d B (reads fp32 x directly, writes fp16).
// grid = 32768 tiles, 128 threads (each thread = 2 channels via float2).
// ============================================================================
__global__ void wino_in_kernel(const float* __restrict__ x) {
    const int t = blockIdx.x;
    const int c2 = threadIdx.x;                 // channel pair: c = 2*c2
    const int tw = t & 63, th = (t >> 6) & 63, b = t >> 12;
    const int h0 = th * 2 - 1, w0 = tw * 2 - 1;

    float2 d[4][4];
    #pragma unroll
    for (int i = 0; i < 4; ++i) {
        const int h = h0 + i;
        const bool hv = (h >= 0) && (h < 128);
        #pragma unroll
        for (int j = 0; j < 4; ++j) {
            const int w_ = w0 + j;
            if (hv && w_ >= 0 && w_ < 128)
                d[i][j] = *reinterpret_cast<const float2*>(
                    x + ((size_t)((b * 128 + h) * 128 + w_)) * 256 + 2 * c2);
            else
                d[i][j] = make_float2(0.0f, 0.0f);
        }
    }
    // rows: Bt
    float2 tr[4][4];
    #pragma unroll
    for (int j = 0; j < 4; ++j) {
        tr[0][j] = make_float2(d[0][j].x - d[2][j].x, d[0][j].y - d[2][j].y);
        tr[1][j] = make_float2(d[1][j].x + d[2][j].x, d[1][j].y + d[2][j].y);
        tr[2][j] = make_float2(d[2][j].x - d[1][j].x, d[2][j].y - d[1][j].y);
        tr[3][j] = make_float2(d[1][j].x - d[3][j].x, d[1][j].y - d[3][j].y);
    }
    // cols: B
    #pragma unroll
    for (int i = 0; i < 4; ++i) {
        float2 v0 = make_float2(tr[i][0].x - tr[i][2].x, tr[i][0].y - tr[i][2].y);
        float2 v1 = make_float2(tr[i][1].x + tr[i][2].x, tr[i][1].y + tr[i][2].y);
        float2 v2 = make_float2(tr[i][2].x - tr[i][1].x, tr[i][2].y - tr[i][1].y);
        float2 v3 = make_float2(tr[i][1].x - tr[i][3].x, tr[i][1].y - tr[i][3].y);
        __half2* dst0 = reinterpret_cast<__half2*>(
            g_V + ((size_t)(i * 4 + 0) * NTIL + t) * 256 + 2 * c2);
        __half2* dst1 = reinterpret_cast<__half2*>(
            g_V + ((size_t)(i * 4 + 1) * NTIL + t) * 256 + 2 * c2);
        __half2* dst2 = reinterpret_cast<__half2*>(
            g_V + ((size_t)(i * 4 + 2) * NTIL + t) * 256 + 2 * c2);
        __half2* dst3 = reinterpret_cast<__half2*>(
            g_V + ((size_t)(i * 4 + 3) * NTIL + t) * 256 + 2 * c2);
        *dst0 = __floats2half2_rn(v0.x, v0.y);
        *dst1 = __floats2half2_rn(v1.x, v1.y);
        *dst2 = __floats2half2_rn(v2.x, v2.y);
        *dst3 = __floats2half2_rn(v3.x, v3.y);
    }
}

// ============================================================================
// Kernel 2: weight transform U = G g Gt. grid=512 (n), block=256 (c).
// ws layout: [kh][kw][c][n] (HWIO).
// ============================================================================
__global__ void wino_w_kernel(const float* __restrict__ ws) {
    const int n = blockIdx.x;
    const int c = threadIdx.x;
    float g[3][3];
    #pragma unroll
    for (int kh = 0; kh < 3; ++kh)
        #pragma unroll
        for (int kw = 0; kw < 3; ++kw)
            g[kh][kw] = ws[((size_t)(kh * 3 + kw) * 256 + c) * 512 + n];
    float u[4][3];
    #pragma unroll
    for (int kw = 0; kw < 3; ++kw) {
        u[0][kw] = g[0][kw];
        u[1][kw] = 0.5f * (g[0][kw] + g[1][kw] + g[2][kw]);
        u[2][kw] = 0.5f * (g[0][kw] - g[1][kw] + g[2][kw]);
        u[3][kw] = g[2][kw];
    }
    #pragma unroll
    for (int r = 0; r < 4; ++r) {
        float U0 = u[r][0];
        float U1 = 0.5f * (u[r][0] + u[r][1] + u[r][2]);
        float U2 = 0.5f * (u[r][0] - u[r][1] + u[r][2]);
        float U3 = u[r][2];
        g_wU[((size_t)(r * 4 + 0) * 512 + n) * 256 + c] = __float2half(U0);
        g_wU[((size_t)(r * 4 + 1) * 512 + n) * 256 + c] = __float2half(U1);
        g_wU[((size_t)(r * 4 + 2) * 512 + n) * 256 + c] = __float2half(U2);
        g_wU[((size_t)(r * 4 + 3) * 512 + n) * 256 + c] = __float2half(U3);
    }
}

// ============================================================================
// Kernel 3: head weight pack.
// ============================================================================
__global__ void cvt_wh_kernel(const float* __restrict__ wc, const float* __restrict__ wr) {
    const int j = blockIdx.x;    // 0..127
    const int c = threadIdx.x;   // 0..511
    float v = 0.0f;
    if (j < 30)      v = wc[c * 30 + j];
    else if (j < 90) v = wr[c * 60 + (j - 30)];
    g_wh[(size_t)j * 512 + c] = __float2half(v);
}

// ============================================================================
// Kernel 4: 16 batched GEMMs  M[comp][t][n] = sum_c V[comp][t][c]*U[comp][n][c]
// grid = 16 * 256 * 2 = 8192.  R4 mainloop: 512 thr, 16 warps (2m x 8n),
// warp tile 64x32, CTA 128x256, K=256 in 4 chunks of 64, 2-stage cp.async.
// ============================================================================
#define GW_A(buf)  ((buf) * 49152u)
#define GW_B(buf)  ((buf) * 49152u + 16384u)
#define GW_SMEM    98304
#define GW_NCH     4

__global__ void __launch_bounds__(512, 1) wino_gemm_kernel()
{
    extern __shared__ char sm[];
    const uint32_t sb = smem_u32(sm);
    const int tid = threadIdx.x;
    const int comp = blockIdx.x >> 9;
    const int mblk = (blockIdx.x >> 1) & 255;
    const int n0 = (blockIdx.x & 1) << 8;
    const int t0 = mblk << 7;

    const int rowA = tid >> 2;
    const int kgA0 = (tid * 2) & 7;
    const int rowB = tid >> 1;
    const int kgB0 = (tid * 4) & 7;
    const uint32_t swA = (uint32_t)(rowA & 7);
    const uint32_t swB = (uint32_t)(rowB & 7);

    const int w = tid >> 5, l = tid & 31;
    const int wm = (w >> 3) * 64, wn = (w & 7) * 32;
    const int lrow = l & 15, hi = l >> 4;
    const uint32_t swL = (uint32_t)(lrow & 7);
    uint32_t aRow[4], bRow[2];
    #pragma unroll
    for (int mt = 0; mt < 4; ++mt) aRow[mt] = (uint32_t)((wm + mt * 16 + lrow) * 128);
    #pragma unroll
    for (int nt = 0; nt < 2; ++nt) bRow[nt] = (uint32_t)((wn + nt * 16 + lrow) * 128);

    float acc[4][4][4];
    #pragma unroll
    for (int mt = 0; mt < 4; ++mt)
        #pragma unroll
        for (int n8 = 0; n8 < 4; ++n8)
            #pragma unroll
            for (int e = 0; e < 4; ++e) acc[mt][n8][e] = 0.0f;

    const __half* Vb = g_V  + ((size_t)comp * NTIL + t0) * 256;
    const __half* Ub = g_wU + ((size_t)comp * 512  + n0) * 256;

    auto load_chunk = [&](int q, int buf) {
        const uint32_t Ab = sb + GW_A(buf), Bb = sb + GW_B(buf);
        const char* srcA = reinterpret_cast<const char*>(Vb + (size_t)rowA * 256 + q * 64);
        #pragma unroll
        for (int i = 0; i < 2; ++i) {
            const int kg = kgA0 + i;
            CP_ASYNC16(Ab + (uint32_t)rowA * 128 + (((uint32_t)kg ^ swA) << 4),
                       srcA + kg * 16, 16);
        }
        const char* srcB = reinterpret_cast<const char*>(Ub + (size_t)rowB * 256 + q * 64);
        #pragma unroll
        for (int i = 0; i < 4; ++i) {
            const int kg = kgB0 + i;
            CP_ASYNC16(Bb + (uint32_t)rowB * 128 + (((uint32_t)kg ^ swB) << 4),
                       srcB + kg * 16, 16);
        }
    };

    load_chunk(0, 0);
    CP_COMMIT();

    #pragma unroll 1
    for (int q = 0; q < GW_NCH; ++q) {
        if (q + 1 < GW_NCH) {
            load_chunk(q + 1, (q + 1) & 1);
            CP_COMMIT();
            CP_WAIT1();
        } else {
            CP_WAIT0();
        }
        __syncthreads();

        const uint32_t Ab = sb + GW_A(q & 1), Bb = sb + GW_B(q & 1);
        #pragma unroll
        for (int ks = 0; ks < 4; ++ks) {
            const uint32_t col = (((uint32_t)(ks * 2 + hi)) ^ swL) << 4;
            uint32_t af[4][4], bf[2][4];
            #pragma unroll
            for (int mt = 0; mt < 4; ++mt) ldm4(af[mt], Ab + aRow[mt] + col);
            #pragma unroll
            for (int nt = 0; nt < 2; ++nt) ldm4(bf[nt], Bb + bRow[nt] + col);
            #pragma unroll
            for (int mt = 0; mt < 4; ++mt)
                #pragma unroll
                for (int n8 = 0; n8 < 4; ++n8)
                    mma16816(acc[mt][n8], af[mt], bf[n8 >> 1][n8 & 1], bf[n8 >> 1][(n8 & 1) + 2]);
        }
        __syncthreads();
    }

    // epilogue: raw fp32 store to g_M
    const int qrow = l >> 2, qcol = (l & 3) * 2;
    float* Mb = g_M + ((size_t)comp * NTIL + t0) * 512 + n0;
    #pragma unroll
    for (int mt = 0; mt < 4; ++mt) {
        #pragma unroll
        for (int n8 = 0; n8 < 4; ++n8) {
            const int ch = wn + n8 * 8 + qcol;
            #pragma unroll
            for (int hlf = 0; hlf < 2; ++hlf) {
                const int m = wm + mt * 16 + qrow + hlf * 8;
                *reinterpret_cast<float2*>(Mb + (size_t)m * 512 + ch) =
                    make_float2(acc[mt][n8][2 * hlf], acc[mt][n8][2 * hlf + 1]);
            }
        }
    }
}

// ============================================================================
// Kernel 5: output transform Y = At M A + bias, relu6 -> g_sh (fp16).
// grid = 32768 tiles, 256 threads (n pair each).
// ============================================================================
__global__ void wino_out_kernel(const float* __restrict__ bias) {
    const int t = blockIdx.x;
    const int n2 = threadIdx.x;             // n = 2*n2
    const int tw = t & 63, th = (t >> 6) & 63, b = t >> 12;

    float2 m[4][4];
    #pragma unroll
    for (int i = 0; i < 4; ++i)
        #pragma unroll
        for (int j = 0; j < 4; ++j)
            m[i][j] = *reinterpret_cast<const float2*>(
                g_M + ((size_t)(i * 4 + j) * NTIL + t) * 512 + 2 * n2);

    float2 s[2][4];
    #pragma unroll
    for (int j = 0; j < 4; ++j) {
        s[0][j] = make_float2(m[0][j].x + m[1][j].x + m[2][j].x,
                              m[0][j].y + m[1][j].y + m[2][j].y);
        s[1][j] = make_float2(m[1][j].x - m[2][j].x - m[3][j].x,
                              m[1][j].y - m[2][j].y - m[3][j].y);
    }
    const float b0 = bias[2 * n2], b1 = bias[2 * n2 + 1];
    #pragma unroll
    for (int dy = 0; dy < 2; ++dy) {
        float2 y0 = make_float2(s[dy][0].x + s[dy][1].x + s[dy][2].x,
                                s[dy][0].y + s[dy][1].y + s[dy][2].y);
        float2 y1 = make_float2(s[dy][1].x - s[dy][2].x - s[dy][3].x,
                                s[dy][1].y - s[dy][2].y - s[dy][3].y);
        const int h = 2 * th + dy;
        #pragma unroll
        for (int dx = 0; dx < 2; ++dx) {
            const float2 yv = dx ? y1 : y0;
            float v0 = fminf(fmaxf(yv.x + b0, 0.0f), 6.0f);
            float v1 = fminf(fmaxf(yv.y + b1, 0.0f), 6.0f);
            const int w_ = 2 * tw + dx;
            *reinterpret_cast<__half2*>(
                g_sh + ((size_t)((b * 128 + h) * 128 + w_)) * 512 + 2 * n2) =
                __floats2half2_rn(v0, v1);
        }
    }
}

// ============================================================================
// Kernel 6: head GEMM M=128/N=128(96 used)/K=512 + bias + softmax + writes.
// (unchanged from R4)
// ============================================================================
#define HD_A(buf)  ((buf) * 32768u)
#define HD_B(buf)  ((buf) * 32768u + 16384u)
#define HD_BIAS    65536u
#define HD_SMEM    66048
#define HD_NCH     8

__global__ void __launch_bounds__(256, 1) head_kernel(const float* __restrict__ bc,
                                                      const float* __restrict__ br,
                                                      float* __restrict__ out)
{
    extern __shared__ char sm[];
    const uint32_t sb = smem_u32(sm);
    const int tid = threadIdx.x;
    const size_t pos0 = (size_t)blockIdx.x * 128;

    float* hb = reinterpret_cast<float*>(sm + HD_BIAS);
    if (tid < 128)
        hb[tid] = (tid < 30) ? bc[tid] : (tid < 90 ? br[tid - 30] : 0.0f);

    const int rowT = tid >> 1;
    const int kg0 = (tid * 4) & 7;
    const uint32_t swT = (uint32_t)(rowT & 7);

    const int w = tid >> 5, l = tid & 31;
    const int wm = (w >> 2) * 64, wn = (w & 3) * 32;
    const int lrow = l & 15, hi = l >> 4;
    const uint32_t swL = (uint32_t)(lrow & 7);
    uint32_t aRow[4], bRow[2];
    #pragma unroll
    for (int mt = 0; mt < 4; ++mt) aRow[mt] = (uint32_t)((wm + mt * 16 + lrow) * 128);
    #pragma unroll
    for (int nt = 0; nt < 2; ++nt) bRow[nt] = (uint32_t)((wn + nt * 16 + lrow) * 128);

    float acc[4][4][4];
    #pragma unroll
    for (int mt = 0; mt < 4; ++mt)
        #pragma unroll
        for (int n8 = 0; n8 < 4; ++n8)
            #pragma unroll
            for (int e = 0; e < 4; ++e) acc[mt][n8][e] = 0.0f;

    auto load_chunk = [&](int q, int buf) {
        const uint32_t Ab = sb + HD_A(buf), Bb = sb + HD_B(buf);
        const char* srcA = reinterpret_cast<const char*>(
            g_sh + (pos0 + rowT) * 512 + q * 64);
        const char* srcB = reinterpret_cast<const char*>(
            g_wh + (size_t)rowT * 512 + q * 64);
        #pragma unroll
        for (int i = 0; i < 4; ++i) {
            const int kg = kg0 + i;
            const uint32_t off = (uint32_t)rowT * 128 + (((uint32_t)kg ^ swT) << 4);
            CP_ASYNC16(Ab + off, srcA + kg * 16, 16);
            CP_ASYNC16(Bb + off, srcB + kg * 16, 16);
        }
    };

    load_chunk(0, 0);
    CP_COMMIT();

    #pragma unroll 1
    for (int q = 0; q < HD_NCH; ++q) {
        if (q + 1 < HD_NCH) {
            load_chunk(q + 1, (q + 1) & 1);
            CP_COMMIT();
            CP_WAIT1();
        } else {
            CP_WAIT0();
        }
        __syncthreads();

        const uint32_t Ab = sb + HD_A(q & 1), Bb = sb + HD_B(q & 1);
        #pragma unroll
        for (int ks = 0; ks < 4; ++ks) {
            const uint32_t col = (((uint32_t)(ks * 2 + hi)) ^ swL) << 4;
            uint32_t af[4][4], bf[2][4];
            #pragma unroll
            for (int mt = 0; mt < 4; ++mt) ldm4(af[mt], Ab + aRow[mt] + col);
            #pragma unroll
            for (int nt = 0; nt < 2; ++nt) ldm4(bf[nt], Bb + bRow[nt] + col);
            #pragma unroll
            for (int mt = 0; mt < 4; ++mt)
                #pragma unroll
                for (int n8 = 0; n8 < 4; ++n8)
                    mma16816(acc[mt][n8], af[mt], bf[n8 >> 1][n8 & 1], bf[n8 >> 1][(n8 & 1) + 2]);
        }
        __syncthreads();
    }

    const int qrow = l >> 2, qcol = (l & 3) * 2;
    #pragma unroll
    for (int mt = 0; mt < 4; ++mt) {
        #pragma unroll
        for (int n8 = 0; n8 < 4; ++n8) {
            const int ch = wn + n8 * 8 + qcol;
            if (ch >= 90) continue;
            const float b0 = hb[ch], b1 = hb[ch + 1];
            #pragma unroll
            for (int hlf = 0; hlf < 2; ++hlf) {
                const int m = wm + mt * 16 + qrow + hlf * 8;
                const size_t pos = pos0 + m;
                const float v0 = acc[mt][n8][2 * hlf]     + b0;
                const float v1 = acc[mt][n8][2 * hlf + 1] + b1;
                if (ch < 30) {
                    *reinterpret_cast<float2*>(out + pos * 30 + ch) = make_float2(v0, v1);
                    const float mx = fmaxf(v0, v1);
                    const float e0 = __expf(v0 - mx), e1 = __expf(v1 - mx);
                    const float inv = 1.0f / (e0 + e1);
                    *reinterpret_cast<float2*>(out + OFF_PROBS + pos * 30 + ch) =
                        make_float2(e0 * inv, e1 * inv);
                } else {
                    *reinterpret_cast<float2*>(out + OFF_DELTAS + pos * 60 + (ch - 30)) =
                        make_float2(v0, v1);
                }
            }
        }
    }
}

// ============================================================================
// Launch
// ============================================================================
extern "C" void kernel_launch(void* const* d_in, const int* in_sizes, int n_in,
                              void* d_out, int out_size) {
    const float* x  = (const float*)d_in[0];
    const float* ws = (const float*)d_in[1];
    const float* bs = (const float*)d_in[2];
    const float* wc = (const float*)d_in[3];
    const float* bc = (const float*)d_in[4];
    const float* wr = (const float*)d_in[5];
    const float* br = (const float*)d_in[6];
    float* out = (float*)d_out;

    cudaFuncSetAttribute(wino_gemm_kernel, cudaFuncAttributeMaxDynamicSharedMemorySize, GW_SMEM);
    cudaFuncSetAttribute(head_kernel, cudaFuncAttributeMaxDynamicSharedMemorySize, HD_SMEM);

    wino_in_kernel<<<NTIL, 128>>>(x);
    wino_w_kernel<<<512, 256>>>(ws);
    cvt_wh_kernel<<<128, 512>>>(wc, wr);
    wino_gemm_kernel<<<8192, 512, GW_SMEM>>>();
    wino_out_kernel<<<NTIL, 256>>>(bs);
    head_kernel<<<1024, 256, HD_SMEM>>>(bc, br, out);
}

// round 8
// speedup vs baseline: 1.7286x; 1.0851x over previous
#include <cuda_runtime.h>
#include <cuda_fp16.h>
#include <cstdint>

// ============================================================================
// RPNHead via Winograd F(2x2,3x3). R8: persistent-loop GEMM (8 components per
// CTA, one warm cp.async pipeline, 32 K-chunks) + M stored in fp16.
// ============================================================================
#define NPOS 131072
#define NTIL 32768
#define OFF_PROBS  3932160
#define OFF_DELTAS 7864320

__device__ __align__(1024) __half g_V [(size_t)16*NTIL*256];   // input transform
__device__ __align__(1024) __half g_wU[(size_t)16*512*256];    // weight transform
__device__ __align__(1024) __half g_M [(size_t)16*NTIL*512];   // GEMM results (fp16)
__device__ __align__(1024) __half g_sh[(size_t)NPOS*512];      // shared acts fp16
__device__ __align__(1024) __half g_wh[(size_t)128*512];       // head W [j][c]

__device__ __forceinline__ uint32_t smem_u32(const void* p) {
    uint32_t a;
    asm("{ .reg .u64 t; cvta.to.shared.u64 t, %1; cvt.u32.u64 %0, t; }"
        : "=r"(a) : "l"(p));
    return a;
}

#define CP_ASYNC16(dst, src, sz) \
    asm volatile("cp.async.cg.shared.global [%0], [%1], 16, %2;" \
        :: "r"((uint32_t)(dst)), "l"(src), "r"((int)(sz)) : "memory")
#define CP_COMMIT() asm volatile("cp.async.commit_group;" ::: "memory")
#define CP_WAIT1()  asm volatile("cp.async.wait_group 1;" ::: "memory")
#define CP_WAIT0()  asm volatile("cp.async.wait_group 0;" ::: "memory")

__device__ __forceinline__ void ldm4(uint32_t* f, uint32_t addr) {
    asm volatile("ldmatrix.sync.aligned.m8n8.x4.shared.b16 {%0,%1,%2,%3}, [%4];"
        : "=r"(f[0]), "=r"(f[1]), "=r"(f[2]), "=r"(f[3]) : "r"(addr));
}
__device__ __forceinline__ void mma16816(float* c, const uint32_t* a,
                                         uint32_t b0, uint32_t b1) {
    asm volatile("mma.sync.aligned.m16n8k16.row.col.f32.f16.f16.f32 "
        "{%0,%1,%2,%3}, {%4,%5,%6,%7}, {%8,%9}, {%0,%1,%2,%3};"
        : "+f"(c[0]), "+f"(c[1]), "+f"(c[2]), "+f"(c[3])
        : "r"(a[0]), "r"(a[1]), "r"(a[2]), "r"(a[3]), "r"(b0), "r"(b1));
}

// ============================================================================
// Kernel 1: input transform V = Bt d B (fp32 x -> fp16 V).
// ============================================================================
__global__ void wino_in_kernel(const float* __restrict__ x) {
    const int t = blockIdx.x;
    const int c2 = threadIdx.x;                 // channel pair
    const int tw = t & 63, th = (t >> 6) & 63, b = t >> 12;
    const int h0 = th * 2 - 1, w0 = tw * 2 - 1;

    float2 d[4][4];
    #pragma unroll
    for (int i = 0; i < 4; ++i) {
        const int h = h0 + i;
        const bool hv = (h >= 0) && (h < 128);
        #pragma unroll
        for (int j = 0; j < 4; ++j) {
            const int w_ = w0 + j;
            if (hv && w_ >= 0 && w_ < 128)
                d[i][j] = *reinterpret_cast<const float2*>(
                    x + ((size_t)((b * 128 + h) * 128 + w_)) * 256 + 2 * c2);
            else
                d[i][j] = make_float2(0.0f, 0.0f);
        }
    }
    float2 tr[4][4];
    #pragma unroll
    for (int j = 0; j < 4; ++j) {
        tr[0][j] = make_float2(d[0][j].x - d[2][j].x, d[0][j].y - d[2][j].y);
        tr[1][j] = make_float2(d[1][j].x + d[2][j].x, d[1][j].y + d[2][j].y);
        tr[2][j] = make_float2(d[2][j].x - d[1][j].x, d[2][j].y - d[1][j].y);
        tr[3][j] = make_float2(d[1][j].x - d[3][j].x, d[1][j].y - d[3][j].y);
    }
    #pragma unroll
    for (int i = 0; i < 4; ++i) {
        float2 v0 = make_float2(tr[i][0].x - tr[i][2].x, tr[i][0].y - tr[i][2].y);
        float2 v1 = make_float2(tr[i][1].x + tr[i][2].x, tr[i][1].y + tr[i][2].y);
        float2 v2 = make_float2(tr[i][2].x - tr[i][1].x, tr[i][2].y - tr[i][1].y);
        float2 v3 = make_float2(tr[i][1].x - tr[i][3].x, tr[i][1].y - tr[i][3].y);
        *reinterpret_cast<__half2*>(g_V + ((size_t)(i*4+0)*NTIL + t)*256 + 2*c2) = __floats2half2_rn(v0.x, v0.y);
        *reinterpret_cast<__half2*>(g_V + ((size_t)(i*4+1)*NTIL + t)*256 + 2*c2) = __floats2half2_rn(v1.x, v1.y);
        *reinterpret_cast<__half2*>(g_V + ((size_t)(i*4+2)*NTIL + t)*256 + 2*c2) = __floats2half2_rn(v2.x, v2.y);
        *reinterpret_cast<__half2*>(g_V + ((size_t)(i*4+3)*NTIL + t)*256 + 2*c2) = __floats2half2_rn(v3.x, v3.y);
    }
}

// ============================================================================
// Kernel 2: weight transform U = G g Gt. grid=512 (n), block=256 (c).
// ============================================================================
__global__ void wino_w_kernel(const float* __restrict__ ws) {
    const int n = blockIdx.x;
    const int c = threadIdx.x;
    float g[3][3];
    #pragma unroll
    for (int kh = 0; kh < 3; ++kh)
        #pragma unroll
        for (int kw = 0; kw < 3; ++kw)
            g[kh][kw] = ws[((size_t)(kh * 3 + kw) * 256 + c) * 512 + n];
    float u[4][3];
    #pragma unroll
    for (int kw = 0; kw < 3; ++kw) {
        u[0][kw] = g[0][kw];
        u[1][kw] = 0.5f * (g[0][kw] + g[1][kw] + g[2][kw]);
        u[2][kw] = 0.5f * (g[0][kw] - g[1][kw] + g[2][kw]);
        u[3][kw] = g[2][kw];
    }
    #pragma unroll
    for (int r = 0; r < 4; ++r) {
        float U0 = u[r][0];
        float U1 = 0.5f * (u[r][0] + u[r][1] + u[r][2]);
        float U2 = 0.5f * (u[r][0] - u[r][1] + u[r][2]);
        float U3 = u[r][2];
        g_wU[((size_t)(r * 4 + 0) * 512 + n) * 256 + c] = __float2half(U0);
        g_wU[((size_t)(r * 4 + 1) * 512 + n) * 256 + c] = __float2half(U1);
        g_wU[((size_t)(r * 4 + 2) * 512 + n) * 256 + c] = __float2half(U2);
        g_wU[((size_t)(r * 4 + 3) * 512 + n) * 256 + c] = __float2half(U3);
    }
}

// ============================================================================
// Kernel 3: head weight pack.
// ============================================================================
__global__ void cvt_wh_kernel(const float* __restrict__ wc, const float* __restrict__ wr) {
    const int j = blockIdx.x;    // 0..127
    const int c = threadIdx.x;   // 0..511
    float v = 0.0f;
    if (j < 30)      v = wc[c * 30 + j];
    else if (j < 90) v = wr[c * 60 + (j - 30)];
    g_wh[(size_t)j * 512 + c] = __float2half(v);
}

// ============================================================================
// Kernel 4: persistent batched GEMM.
// grid = 1024: mblk(256) x nhalf(2) x comp-half(2). Each CTA loops 8 comps
// (32 K-chunks) through ONE warm 2-stage cp.async pipeline. M stored fp16.
// 512 thr, 16 warps (2m x 8n), warp tile 64x32, CTA 128x256.
// ============================================================================
#define GW_A(buf)  ((buf) * 49152u)
#define GW_B(buf)  ((buf) * 49152u + 16384u)
#define GW_SMEM    98304
#define GW_NQQ     32     // 8 comps * 4 chunks

__global__ void __launch_bounds__(512, 1) wino_gemm_kernel()
{
    extern __shared__ char sm[];
    const uint32_t sb = smem_u32(sm);
    const int tid = threadIdx.x;
    const int mblk = blockIdx.x >> 2;
    const int n0 = ((blockIdx.x >> 1) & 1) << 8;
    const int c0 = (blockIdx.x & 1) << 3;       // comp base: 0 or 8
    const int t0 = mblk << 7;

    const int rowA = tid >> 2;
    const int kgA0 = (tid * 2) & 7;
    const int rowB = tid >> 1;
    const int kgB0 = (tid * 4) & 7;
    const uint32_t swA = (uint32_t)(rowA & 7);
    const uint32_t swB = (uint32_t)(rowB & 7);

    const int w = tid >> 5, l = tid & 31;
    const int wm = (w >> 3) * 64, wn = (w & 7) * 32;
    const int lrow = l & 15, hi = l >> 4;
    const uint32_t swL = (uint32_t)(lrow & 7);
    uint32_t aRow[4], bRow[2];
    #pragma unroll
    for (int mt = 0; mt < 4; ++mt) aRow[mt] = (uint32_t)((wm + mt * 16 + lrow) * 128);
    #pragma unroll
    for (int nt = 0; nt < 2; ++nt) bRow[nt] = (uint32_t)((wn + nt * 16 + lrow) * 128);

    float acc[4][4][4];
    #pragma unroll
    for (int mt = 0; mt < 4; ++mt)
        #pragma unroll
        for (int n8 = 0; n8 < 4; ++n8)
            #pragma unroll
            for (int e = 0; e < 4; ++e) acc[mt][n8][e] = 0.0f;

    auto load_chunk = [&](int qq, int buf) {
        const int comp = c0 + (qq >> 2), q = qq & 3;
        const uint32_t Ab = sb + GW_A(buf), Bb = sb + GW_B(buf);
        const char* srcA = reinterpret_cast<const char*>(
            g_V + ((size_t)comp * NTIL + t0 + rowA) * 256 + q * 64);
        #pragma unroll
        for (int i = 0; i < 2; ++i) {
            const int kg = kgA0 + i;
            CP_ASYNC16(Ab + (uint32_t)rowA * 128 + (((uint32_t)kg ^ swA) << 4),
                       srcA + kg * 16, 16);
        }
        const char* srcB = reinterpret_cast<const char*>(
            g_wU + ((size_t)comp * 512 + n0 + rowB) * 256 + q * 64);
        #pragma unroll
        for (int i = 0; i < 4; ++i) {
            const int kg = kgB0 + i;
            CP_ASYNC16(Bb + (uint32_t)rowB * 128 + (((uint32_t)kg ^ swB) << 4),
                       srcB + kg * 16, 16);
        }
    };

    load_chunk(0, 0);
    CP_COMMIT();

    const int qrow = l >> 2, qcol = (l & 3) * 2;

    #pragma unroll 1
    for (int qq = 0; qq < GW_NQQ; ++qq) {
        if (qq + 1 < GW_NQQ) {
            load_chunk(qq + 1, (qq + 1) & 1);
            CP_COMMIT();
            CP_WAIT1();
        } else {
            CP_WAIT0();
        }
        __syncthreads();

        const uint32_t Ab = sb + GW_A(qq & 1), Bb = sb + GW_B(qq & 1);
        #pragma unroll
        for (int ks = 0; ks < 4; ++ks) {
            const uint32_t col = (((uint32_t)(ks * 2 + hi)) ^ swL) << 4;
            uint32_t af[4][4], bf[2][4];
            #pragma unroll
            for (int mt = 0; mt < 4; ++mt) ldm4(af[mt], Ab + aRow[mt] + col);
            #pragma unroll
            for (int nt = 0; nt < 2; ++nt) ldm4(bf[nt], Bb + bRow[nt] + col);
            #pragma unroll
            for (int mt = 0; mt < 4; ++mt)
                #pragma unroll
                for (int n8 = 0; n8 < 4; ++n8)
                    mma16816(acc[mt][n8], af[mt], bf[n8 >> 1][n8 & 1], bf[n8 >> 1][(n8 & 1) + 2]);
        }
        __syncthreads();

        if ((qq & 3) == 3) {
            // epilogue for comp = c0 + (qq>>2): fp16 store + acc reset
            const int comp = c0 + (qq >> 2);
            __half* Mb = g_M + ((size_t)comp * NTIL + t0) * 512 + n0;
            #pragma unroll
            for (int mt = 0; mt < 4; ++mt) {
                #pragma unroll
                for (int n8 = 0; n8 < 4; ++n8) {
                    const int ch = wn + n8 * 8 + qcol;
                    #pragma unroll
                    for (int hlf = 0; hlf < 2; ++hlf) {
                        const int m = wm + mt * 16 + qrow + hlf * 8;
                        *reinterpret_cast<__half2*>(Mb + (size_t)m * 512 + ch) =
                            __floats2half2_rn(acc[mt][n8][2 * hlf], acc[mt][n8][2 * hlf + 1]);
                        acc[mt][n8][2 * hlf] = 0.0f;
                        acc[mt][n8][2 * hlf + 1] = 0.0f;
                    }
                }
            }
        }
    }
}

// ============================================================================
// Kernel 5: output transform Y = At M A + bias, relu6 -> g_sh (fp16 M input).
// ============================================================================
__global__ void wino_out_kernel(const float* __restrict__ bias) {
    const int t = blockIdx.x;
    const int n2 = threadIdx.x;             // n = 2*n2
    const int tw = t & 63, th = (t >> 6) & 63, b = t >> 12;

    float2 m[4][4];
    #pragma unroll
    for (int i = 0; i < 4; ++i)
        #pragma unroll
        for (int j = 0; j < 4; ++j) {
            __half2 hm = *reinterpret_cast<const __half2*>(
                g_M + ((size_t)(i * 4 + j) * NTIL + t) * 512 + 2 * n2);
            m[i][j] = __half22float2(hm);
        }

    float2 s[2][4];
    #pragma unroll
    for (int j = 0; j < 4; ++j) {
        s[0][j] = make_float2(m[0][j].x + m[1][j].x + m[2][j].x,
                              m[0][j].y + m[1][j].y + m[2][j].y);
        s[1][j] = make_float2(m[1][j].x - m[2][j].x - m[3][j].x,
                              m[1][j].y - m[2][j].y - m[3][j].y);
    }
    const float b0 = bias[2 * n2], b1 = bias[2 * n2 + 1];
    #pragma unroll
    for (int dy = 0; dy < 2; ++dy) {
        float2 y0 = make_float2(s[dy][0].x + s[dy][1].x + s[dy][2].x,
                                s[dy][0].y + s[dy][1].y + s[dy][2].y);
        float2 y1 = make_float2(s[dy][1].x - s[dy][2].x - s[dy][3].x,
                                s[dy][1].y - s[dy][2].y - s[dy][3].y);
        const int h = 2 * th + dy;
        #pragma unroll
        for (int dx = 0; dx < 2; ++dx) {
            const float2 yv = dx ? y1 : y0;
            float v0 = fminf(fmaxf(yv.x + b0, 0.0f), 6.0f);
            float v1 = fminf(fmaxf(yv.y + b1, 0.0f), 6.0f);
            const int w_ = 2 * tw + dx;
            *reinterpret_cast<__half2*>(
                g_sh + ((size_t)((b * 128 + h) * 128 + w_)) * 512 + 2 * n2) =
                __floats2half2_rn(v0, v1);
        }
    }
}

// ============================================================================
// Kernel 6: head GEMM M=128/N=128(96 used)/K=512 + bias + softmax + writes.
// ============================================================================
#define HD_A(buf)  ((buf) * 32768u)
#define HD_B(buf)  ((buf) * 32768u + 16384u)
#define HD_BIAS    65536u
#define HD_SMEM    66048
#define HD_NCH     8

__global__ void __launch_bounds__(256, 1) head_kernel(const float* __restrict__ bc,
                                                      const float* __restrict__ br,
                                                      float* __restrict__ out)
{
    extern __shared__ char sm[];
    const uint32_t sb = smem_u32(sm);
    const int tid = threadIdx.x;
    const size_t pos0 = (size_t)blockIdx.x * 128;

    float* hb = reinterpret_cast<float*>(sm + HD_BIAS);
    if (tid < 128)
        hb[tid] = (tid < 30) ? bc[tid] : (tid < 90 ? br[tid - 30] : 0.0f);

    const int rowT = tid >> 1;
    const int kg0 = (tid * 4) & 7;
    const uint32_t swT = (uint32_t)(rowT & 7);

    const int w = tid >> 5, l = tid & 31;
    const int wm = (w >> 2) * 64, wn = (w & 3) * 32;
    const int lrow = l & 15, hi = l >> 4;
    const uint32_t swL = (uint32_t)(lrow & 7);
    uint32_t aRow[4], bRow[2];
    #pragma unroll
    for (int mt = 0; mt < 4; ++mt) aRow[mt] = (uint32_t)((wm + mt * 16 + lrow) * 128);
    #pragma unroll
    for (int nt = 0; nt < 2; ++nt) bRow[nt] = (uint32_t)((wn + nt * 16 + lrow) * 128);

    float acc[4][4][4];
    #pragma unroll
    for (int mt = 0; mt < 4; ++mt)
        #pragma unroll
        for (int n8 = 0; n8 < 4; ++n8)
            #pragma unroll
            for (int e = 0; e < 4; ++e) acc[mt][n8][e] = 0.0f;

    auto load_chunk = [&](int q, int buf) {
        const uint32_t Ab = sb + HD_A(buf), Bb = sb + HD_B(buf);
        const char* srcA = reinterpret_cast<const char*>(
            g_sh + (pos0 + rowT) * 512 + q * 64);
        const char* srcB = reinterpret_cast<const char*>(
            g_wh + (size_t)rowT * 512 + q * 64);
        #pragma unroll
        for (int i = 0; i < 4; ++i) {
            const int kg = kg0 + i;
            const uint32_t off = (uint32_t)rowT * 128 + (((uint32_t)kg ^ swT) << 4);
            CP_ASYNC16(Ab + off, srcA + kg * 16, 16);
            CP_ASYNC16(Bb + off, srcB + kg * 16, 16);
        }
    };

    load_chunk(0, 0);
    CP_COMMIT();

    #pragma unroll 1
    for (int q = 0; q < HD_NCH; ++q) {
        if (q + 1 < HD_NCH) {
            load_chunk(q + 1, (q + 1) & 1);
            CP_COMMIT();
            CP_WAIT1();
        } else {
            CP_WAIT0();
        }
        __syncthreads();

        const uint32_t Ab = sb + HD_A(q & 1), Bb = sb + HD_B(q & 1);
        #pragma unroll
        for (int ks = 0; ks < 4; ++ks) {
            const uint32_t col = (((uint32_t)(ks * 2 + hi)) ^ swL) << 4;
            uint32_t af[4][4], bf[2][4];
            #pragma unroll
            for (int mt = 0; mt < 4; ++mt) ldm4(af[mt], Ab + aRow[mt] + col);
            #pragma unroll
            for (int nt = 0; nt < 2; ++nt) ldm4(bf[nt], Bb + bRow[nt] + col);
            #pragma unroll
            for (int mt = 0; mt < 4; ++mt)
                #pragma unroll
                for (int n8 = 0; n8 < 4; ++n8)
                    mma16816(acc[mt][n8], af[mt], bf[n8 >> 1][n8 & 1], bf[n8 >> 1][(n8 & 1) + 2]);
        }
        __syncthreads();
    }

    const int qrow = l >> 2, qcol = (l & 3) * 2;
    #pragma unroll
    for (int mt = 0; mt < 4; ++mt) {
        #pragma unroll
        for (int n8 = 0; n8 < 4; ++n8) {
            const int ch = wn + n8 * 8 + qcol;
            if (ch >= 90) continue;
            const float b0 = hb[ch], b1 = hb[ch + 1];
            #pragma unroll
            for (int hlf = 0; hlf < 2; ++hlf) {
                const int m = wm + mt * 16 + qrow + hlf * 8;
                const size_t pos = pos0 + m;
                const float v0 = acc[mt][n8][2 * hlf]     + b0;
                const float v1 = acc[mt][n8][2 * hlf + 1] + b1;
                if (ch < 30) {
                    *reinterpret_cast<float2*>(out + pos * 30 + ch) = make_float2(v0, v1);
                    const float mx = fmaxf(v0, v1);
                    const float e0 = __expf(v0 - mx), e1 = __expf(v1 - mx);
                    const float inv = 1.0f / (e0 + e1);
                    *reinterpret_cast<float2*>(out + OFF_PROBS + pos * 30 + ch) =
                        make_float2(e0 * inv, e1 * inv);
                } else {
                    *reinterpret_cast<float2*>(out + OFF_DELTAS + pos * 60 + (ch - 30)) =
                        make_float2(v0, v1);
                }
            }
        }
    }
}

// ============================================================================
// Launch
// ============================================================================
extern "C" void kernel_launch(void* const* d_in, const int* in_sizes, int n_in,
                              void* d_out, int out_size) {
    const float* x  = (const float*)d_in[0];
    const float* ws = (const float*)d_in[1];
    const float* bs = (const float*)d_in[2];
    const float* wc = (const float*)d_in[3];
    const float* bc = (const float*)d_in[4];
    const float* wr = (const float*)d_in[5];
    const float* br = (const float*)d_in[6];
    float* out = (float*)d_out;

    cudaFuncSetAttribute(wino_gemm_kernel, cudaFuncAttributeMaxDynamicSharedMemorySize, GW_SMEM);
    cudaFuncSetAttribute(head_kernel, cudaFuncAttributeMaxDynamicSharedMemorySize, HD_SMEM);

    wino_in_kernel<<<NTIL, 128>>>(x);
    wino_w_kernel<<<512, 256>>>(ws);
    cvt_wh_kernel<<<128, 512>>>(wc, wr);
    wino_gemm_kernel<<<1024, 512, GW_SMEM>>>();
    wino_out_kernel<<<NTIL, 256>>>(bs);
    head_kernel<<<1024, 256, HD_SMEM>>>(bc, br, out);
}